// round 1
// baseline (speedup 1.0000x reference)
#include <cuda_runtime.h>
#include <cuda_bf16.h>

// B = 1048576 rows, C = 64, K = 4. out[b] = mix0*lut_out + mix1*add1 + mix2*add2
// where s = x[b,:] @ softmax(cp, axis=0).
//
// Strategy: pure HBM-streaming kernel. 16 threads cooperate per row (1x LDG.128
// each -> fully coalesced 512B per warp over 2 consecutive rows). Tiny params
// (probs / sigmoid(lut) / softmax(mix)) are recomputed per block in smem from
// L2-resident inputs; cost is negligible vs the 256MB x stream.

#define ROWS_PER_BLOCK 16
#define NTHREADS 256

__global__ void __launch_bounds__(NTHREADS)
lab_fused_kernel(const float* __restrict__ x,
                 const float* __restrict__ cp,    // [64,4] row-major
                 const float* __restrict__ lut,   // [2,2,2,2] flattened = 16
                 const float* __restrict__ mix,   // [3]
                 float* __restrict__ out)
{
    __shared__ float4 s_probs[64];   // probs[c] = {p_c0, p_c1, p_c2, p_c3}
    __shared__ float  s_inv[4];
    __shared__ float  s_lut[16];
    __shared__ float  s_mix[3];
    float* s_probs_f = reinterpret_cast<float*>(s_probs);

    const int tid = threadIdx.x;

    // ---- per-block parameter prep (tiny, L2-resident inputs) ----
    float e = __expf(cp[tid]);          // cp has exactly 256 elements
    s_probs_f[tid] = e;

    if (tid >= 32 && tid < 48) {
        int i = tid - 32;
        s_lut[i] = 1.0f / (1.0f + __expf(-lut[i]));
    }
    if (tid == 64) {
        float m0 = __expf(mix[0]);
        float m1 = __expf(mix[1]);
        float m2 = __expf(mix[2]);
        float inv = 1.0f / (m0 + m1 + m2);
        s_mix[0] = m0 * inv;
        s_mix[1] = m1 * inv;
        s_mix[2] = m2 * inv;
    }
    __syncthreads();

    if (tid < 4) {                       // column sums over C=64
        float sum = 0.0f;
        #pragma unroll
        for (int c = 0; c < 64; ++c) sum += s_probs_f[c * 4 + tid];
        s_inv[tid] = 1.0f / sum;
    }
    __syncthreads();

    s_probs_f[tid] *= s_inv[tid & 3];    // normalize: probs[c][k]
    __syncthreads();

    // ---- streaming body: 16 threads per row ----
    const int row = blockIdx.x * ROWS_PER_BLOCK + (tid >> 4);
    const int j   = tid & 15;            // lane within row group

    const float4 xv = reinterpret_cast<const float4*>(x)[row * 16 + j];

    const float4 p0 = s_probs[j * 4 + 0];
    const float4 p1 = s_probs[j * 4 + 1];
    const float4 p2 = s_probs[j * 4 + 2];
    const float4 p3 = s_probs[j * 4 + 3];

    float a0 = xv.x * p0.x + xv.y * p1.x + xv.z * p2.x + xv.w * p3.x;
    float a1 = xv.x * p0.y + xv.y * p1.y + xv.z * p2.y + xv.w * p3.y;
    float a2 = xv.x * p0.z + xv.y * p1.z + xv.z * p2.z + xv.w * p3.z;
    float a3 = xv.x * p0.w + xv.y * p1.w + xv.z * p2.w + xv.w * p3.w;

    // reduce partial dots across the 16-lane group
    #pragma unroll
    for (int off = 8; off >= 1; off >>= 1) {
        a0 += __shfl_down_sync(0xffffffffu, a0, off, 16);
        a1 += __shfl_down_sync(0xffffffffu, a1, off, 16);
        a2 += __shfl_down_sync(0xffffffffu, a2, off, 16);
        a3 += __shfl_down_sync(0xffffffffu, a3, off, 16);
    }

    if (j == 0) {
        const float s0 = a0, s1 = a1, s2 = a2, s3 = a3;

        // addition path
        const float add = s0 + s1 + s2;
        const float ao1 = fminf(fmaxf(add - 2.0f, 0.0f), 1.0f);
        const float ao2 = (add >= 2.0f) ? 1.0f : 0.0f;

        // multilinear LUT contraction over sigmoid(lut)[2,2,2,2]
        // weight for bit 0 of dim i is s_i; bit 1 is (1 - s_i).
        const float w3b = 1.0f - s3;
        float u0 = s_lut[ 0] * s3 + s_lut[ 1] * w3b;
        float u1 = s_lut[ 2] * s3 + s_lut[ 3] * w3b;
        float u2 = s_lut[ 4] * s3 + s_lut[ 5] * w3b;
        float u3 = s_lut[ 6] * s3 + s_lut[ 7] * w3b;
        float u4 = s_lut[ 8] * s3 + s_lut[ 9] * w3b;
        float u5 = s_lut[10] * s3 + s_lut[11] * w3b;
        float u6 = s_lut[12] * s3 + s_lut[13] * w3b;
        float u7 = s_lut[14] * s3 + s_lut[15] * w3b;

        const float w2b = 1.0f - s2;
        const float v0 = u0 * s2 + u1 * w2b;
        const float v1 = u2 * s2 + u3 * w2b;
        const float v2 = u4 * s2 + u5 * w2b;
        const float v3 = u6 * s2 + u7 * w2b;

        const float w1b = 1.0f - s1;
        const float r0 = v0 * s1 + v1 * w1b;
        const float r1 = v2 * s1 + v3 * w1b;

        const float lut_out = r0 * s0 + r1 * (1.0f - s0);

        out[row] = s_mix[0] * lut_out + s_mix[1] * ao1 + s_mix[2] * ao2;
    }
}

extern "C" void kernel_launch(void* const* d_in, const int* in_sizes, int n_in,
                              void* d_out, int out_size)
{
    const float* x   = (const float*)d_in[0];   // [B, 64]
    const float* cp  = (const float*)d_in[1];   // [64, 4]
    const float* lut = (const float*)d_in[2];   // [2,2,2,2] = 16
    const float* mix = (const float*)d_in[3];   // [3]
    float* out = (float*)d_out;                 // [B, 1]

    const int B = in_sizes[0] / 64;
    const int blocks = B / ROWS_PER_BLOCK;      // B = 1048576 -> 65536

    lab_fused_kernel<<<blocks, NTHREADS>>>(x, cp, lut, mix, out);
}

// round 2
// speedup vs baseline: 3.5191x; 3.5191x over previous
#include <cuda_runtime.h>
#include <cuda_bf16.h>

// B = 1048576 rows, C = 64, K = 4.
// out[b] = mix0*lut(s) + mix1*clip(s0+s1+s2-2,0,1) + mix2*(s0+s1+s2>=2)
// with s = x[b,:] @ softmax(cp, axis=0).
//
// Design: HBM-streaming, smem-staged tiles, ONE thread per row, no shuffles.
//  - cp.async.cg stages 128 rows x 256B into padded smem (17 float4 / row
//    -> conflict-free per-row LDS.128).
//  - probs/sigmoid(lut)/softmax(mix) computed once per block (grid-stride).
//  - probs read as uniform-broadcast LDS.128 (N=1, no conflict penalty).

#define NTHREADS   128
#define TILE_ROWS  128
#define ROW_F4     17          // 16 data float4 + 1 pad -> conflict-free

__device__ __forceinline__ void cp_async16(void* smem_dst, const void* gsrc) {
    unsigned s = (unsigned)__cvta_generic_to_shared(smem_dst);
    asm volatile("cp.async.cg.shared.global [%0], [%1], 16;\n" :: "r"(s), "l"(gsrc));
}

__global__ void __launch_bounds__(NTHREADS)
lab_fused_kernel(const float* __restrict__ x,
                 const float* __restrict__ cp,    // [64,4]
                 const float* __restrict__ lut,   // 16
                 const float* __restrict__ mix,   // 3
                 float* __restrict__ out,
                 int ntiles)
{
    __shared__ float4 s_x[TILE_ROWS * ROW_F4];   // 34816 B
    __shared__ float4 s_probs[64];               // probs[c] = {p_c0..p_c3}
    __shared__ float  s_lut[16];
    __shared__ float  s_mix[3];
    __shared__ float  s_inv[4];
    float* s_probs_f = reinterpret_cast<float*>(s_probs);

    const int tid = threadIdx.x;

    // ---- per-block parameter prep (once, amortized over many tiles) ----
    s_probs_f[tid]       = __expf(cp[tid]);
    s_probs_f[tid + 128] = __expf(cp[tid + 128]);
    if (tid < 16) s_lut[tid] = 1.0f / (1.0f + __expf(-lut[tid]));
    if (tid == 32) {
        float m0 = __expf(mix[0]), m1 = __expf(mix[1]), m2 = __expf(mix[2]);
        float inv = 1.0f / (m0 + m1 + m2);
        s_mix[0] = m0 * inv; s_mix[1] = m1 * inv; s_mix[2] = m2 * inv;
    }
    __syncthreads();

    if (tid < 32) {                    // column sums via warp reduction
        float acc = 0.0f;
        #pragma unroll
        for (int i = 0; i < 8; ++i) acc += s_probs_f[tid + 32 * i];
        #pragma unroll
        for (int off = 16; off >= 4; off >>= 1)
            acc += __shfl_down_sync(0xffffffffu, acc, off);
        if (tid < 4) s_inv[tid] = 1.0f / acc;   // acc_t sums entries with k = t%4
    }
    __syncthreads();

    s_probs_f[tid]       *= s_inv[tid & 3];
    s_probs_f[tid + 128] *= s_inv[tid & 3];
    __syncthreads();

    const float4* __restrict__ x4 = reinterpret_cast<const float4*>(x);

    // ---- grid-stride over tiles of 128 rows ----
    for (int tile = blockIdx.x; tile < ntiles; tile += gridDim.x) {
        const size_t base_f4 = (size_t)tile * (TILE_ROWS * 16);

        // stage tile: fully coalesced global reads, padded smem writes
        #pragma unroll
        for (int i = 0; i < 16; ++i) {
            int l = tid + NTHREADS * i;          // linear float4 in tile
            int r = l >> 4, f = l & 15;
            cp_async16(&s_x[r * ROW_F4 + f], &x4[base_f4 + l]);
        }
        asm volatile("cp.async.commit_group;\n" ::: "memory");
        asm volatile("cp.async.wait_group 0;\n" ::: "memory");
        __syncthreads();

        // each thread computes its own row: no inter-thread reduction
        const float4* __restrict__ xr = &s_x[tid * ROW_F4];
        float a0 = 0.0f, a1 = 0.0f, a2 = 0.0f, a3 = 0.0f;
        #pragma unroll
        for (int f = 0; f < 16; ++f) {
            const float4 xv = xr[f];
            const float4 p0 = s_probs[4 * f + 0];   // uniform broadcast
            const float4 p1 = s_probs[4 * f + 1];
            const float4 p2 = s_probs[4 * f + 2];
            const float4 p3 = s_probs[4 * f + 3];
            a0 += xv.x * p0.x; a1 += xv.x * p0.y; a2 += xv.x * p0.z; a3 += xv.x * p0.w;
            a0 += xv.y * p1.x; a1 += xv.y * p1.y; a2 += xv.y * p1.z; a3 += xv.y * p1.w;
            a0 += xv.z * p2.x; a1 += xv.z * p2.y; a2 += xv.z * p2.z; a3 += xv.z * p2.w;
            a0 += xv.w * p3.x; a1 += xv.w * p3.y; a2 += xv.w * p3.z; a3 += xv.w * p3.w;
        }

        const float s0 = a0, s1 = a1, s2 = a2, s3 = a3;

        // addition path
        const float add = s0 + s1 + s2;
        const float ao1 = fminf(fmaxf(add - 2.0f, 0.0f), 1.0f);
        const float ao2 = (add >= 2.0f) ? 1.0f : 0.0f;

        // multilinear contraction over sigmoid(lut)[2,2,2,2]; bit0 -> s, bit1 -> 1-s
        const float w3b = 1.0f - s3;
        const float u0 = s_lut[ 0] * s3 + s_lut[ 1] * w3b;
        const float u1 = s_lut[ 2] * s3 + s_lut[ 3] * w3b;
        const float u2 = s_lut[ 4] * s3 + s_lut[ 5] * w3b;
        const float u3 = s_lut[ 6] * s3 + s_lut[ 7] * w3b;
        const float u4 = s_lut[ 8] * s3 + s_lut[ 9] * w3b;
        const float u5 = s_lut[10] * s3 + s_lut[11] * w3b;
        const float u6 = s_lut[12] * s3 + s_lut[13] * w3b;
        const float u7 = s_lut[14] * s3 + s_lut[15] * w3b;

        const float w2b = 1.0f - s2;
        const float v0 = u0 * s2 + u1 * w2b;
        const float v1 = u2 * s2 + u3 * w2b;
        const float v2 = u4 * s2 + u5 * w2b;
        const float v3 = u6 * s2 + u7 * w2b;

        const float w1b = 1.0f - s1;
        const float r0 = v0 * s1 + v1 * w1b;
        const float r1 = v2 * s1 + v3 * w1b;

        const float lut_out = r0 * s0 + r1 * (1.0f - s0);

        out[tile * TILE_ROWS + tid] = s_mix[0] * lut_out + s_mix[1] * ao1 + s_mix[2] * ao2;

        __syncthreads();   // protect s_x before next tile's cp.async overwrite
    }
}

extern "C" void kernel_launch(void* const* d_in, const int* in_sizes, int n_in,
                              void* d_out, int out_size)
{
    const float* x   = (const float*)d_in[0];   // [B, 64]
    const float* cp  = (const float*)d_in[1];   // [64, 4]
    const float* lut = (const float*)d_in[2];   // 16
    const float* mix = (const float*)d_in[3];   // 3
    float* out = (float*)d_out;

    const int B      = in_sizes[0] / 64;
    const int ntiles = B / TILE_ROWS;           // 8192

    const int grid = 1024;                      // grid-stride, 8 tiles per block
    lab_fused_kernel<<<grid, NTHREADS>>>(x, cp, lut, mix, out, ntiles);
}

// round 3
// speedup vs baseline: 3.9712x; 1.1285x over previous
#include <cuda_runtime.h>
#include <cuda_bf16.h>

// B = 1048576 rows, C = 64, K = 4.
// out[b] = mix0*lut(s) + mix1*clip(s0+s1+s2-2,0,1) + mix2*(s0+s1+s2>=2)
// with s = x[b,:] @ softmax(cp, axis=0).
//
// Round-3 design: double-buffered cp.async pipeline (overlap DRAM with compute),
// XOR-swizzled smem tiles (32KB/stage, conflict-free writes AND per-row reads),
// one thread per row, epilogue fully in-thread (no shuffles).

#define NTHREADS   128
#define TILE_ROWS  128
#define STAGE_F4   (TILE_ROWS * 16)      // 2048 float4 = 32KB per stage

__device__ __forceinline__ void cp_async16(void* smem_dst, const void* gsrc) {
    unsigned s = (unsigned)__cvta_generic_to_shared(smem_dst);
    asm volatile("cp.async.cg.shared.global [%0], [%1], 16;\n" :: "r"(s), "l"(gsrc));
}

extern __shared__ float4 g_smem[];   // [2*STAGE_F4] x-tiles | [64] probs | 24 floats params

__global__ void __launch_bounds__(NTHREADS)
lab_fused_kernel(const float* __restrict__ x,
                 const float* __restrict__ cp,    // [64,4]
                 const float* __restrict__ lut,   // 16
                 const float* __restrict__ mix,   // 3
                 float* __restrict__ out,
                 int ntiles)
{
    float4* s_x     = g_smem;                    // 2 stages
    float4* s_probs = g_smem + 2 * STAGE_F4;     // probs[c] = {p_c0..p_c3}
    float*  s_tail  = reinterpret_cast<float*>(s_probs + 64);
    float*  s_lut   = s_tail;        // 16
    float*  s_mix   = s_tail + 16;   // 3
    float*  s_inv   = s_tail + 20;   // 4
    float*  s_probs_f = reinterpret_cast<float*>(s_probs);

    const int tid = threadIdx.x;

    // ---- per-block parameter prep (once) ----
    s_probs_f[tid]       = __expf(cp[tid]);
    s_probs_f[tid + 128] = __expf(cp[tid + 128]);
    if (tid < 16) s_lut[tid] = 1.0f / (1.0f + __expf(-lut[tid]));
    if (tid == 32) {
        float m0 = __expf(mix[0]), m1 = __expf(mix[1]), m2 = __expf(mix[2]);
        float inv = 1.0f / (m0 + m1 + m2);
        s_mix[0] = m0 * inv; s_mix[1] = m1 * inv; s_mix[2] = m2 * inv;
    }
    __syncthreads();

    if (tid < 32) {                              // column sums via warp reduction
        float acc = 0.0f;
        #pragma unroll
        for (int i = 0; i < 8; ++i) acc += s_probs_f[tid + 32 * i];
        #pragma unroll
        for (int off = 16; off >= 4; off >>= 1)
            acc += __shfl_down_sync(0xffffffffu, acc, off);
        if (tid < 4) s_inv[tid] = 1.0f / acc;
    }
    __syncthreads();

    s_probs_f[tid]       *= s_inv[tid & 3];
    s_probs_f[tid + 128] *= s_inv[tid & 3];
    __syncthreads();

    const float4* __restrict__ x4 = reinterpret_cast<const float4*>(x);
    const int stride = gridDim.x;

    // XOR-swizzled tile stage: write (r,f) at r*16 + ((f+r)&15)
    auto load_tile = [&](int tile, int stage) {
        const size_t base_f4 = (size_t)tile * STAGE_F4;
        float4* dst = s_x + stage * STAGE_F4;
        #pragma unroll
        for (int i = 0; i < 16; ++i) {
            int l = tid + NTHREADS * i;          // consecutive threads -> coalesced
            int r = l >> 4, f = l & 15;
            cp_async16(&dst[r * 16 + ((f + r) & 15)], &x4[base_f4 + l]);
        }
    };

    // ---- software pipeline: prefetch next while computing current ----
    int tile = blockIdx.x;
    if (tile < ntiles) load_tile(tile, 0);
    asm volatile("cp.async.commit_group;\n" ::: "memory");

    int buf = 0;
    for (; tile < ntiles; tile += stride) {
        const int nxt = tile + stride;
        if (nxt < ntiles) load_tile(nxt, buf ^ 1);
        asm volatile("cp.async.commit_group;\n" ::: "memory");
        asm volatile("cp.async.wait_group 1;\n" ::: "memory");  // current buf ready
        __syncthreads();

        const float4* __restrict__ xr = s_x + buf * STAGE_F4 + tid * 16;
        float a0 = 0.0f, a1 = 0.0f, a2 = 0.0f, a3 = 0.0f;
        #pragma unroll
        for (int f = 0; f < 16; ++f) {
            const float4 xv = xr[(f + tid) & 15];     // de-swizzle, conflict-free
            const float4 p0 = s_probs[4 * f + 0];     // uniform broadcast
            const float4 p1 = s_probs[4 * f + 1];
            const float4 p2 = s_probs[4 * f + 2];
            const float4 p3 = s_probs[4 * f + 3];
            a0 = fmaf(xv.x, p0.x, a0); a1 = fmaf(xv.x, p0.y, a1);
            a2 = fmaf(xv.x, p0.z, a2); a3 = fmaf(xv.x, p0.w, a3);
            a0 = fmaf(xv.y, p1.x, a0); a1 = fmaf(xv.y, p1.y, a1);
            a2 = fmaf(xv.y, p1.z, a2); a3 = fmaf(xv.y, p1.w, a3);
            a0 = fmaf(xv.z, p2.x, a0); a1 = fmaf(xv.z, p2.y, a1);
            a2 = fmaf(xv.z, p2.z, a2); a3 = fmaf(xv.z, p2.w, a3);
            a0 = fmaf(xv.w, p3.x, a0); a1 = fmaf(xv.w, p3.y, a1);
            a2 = fmaf(xv.w, p3.z, a2); a3 = fmaf(xv.w, p3.w, a3);
        }

        const float s0 = a0, s1 = a1, s2 = a2, s3 = a3;

        // addition path
        const float add = s0 + s1 + s2;
        const float ao1 = fminf(fmaxf(add - 2.0f, 0.0f), 1.0f);
        const float ao2 = (add >= 2.0f) ? 1.0f : 0.0f;

        // multilinear contraction over sigmoid(lut)[2,2,2,2]; bit0 -> s, bit1 -> 1-s
        const float w3b = 1.0f - s3;
        const float u0 = s_lut[ 0] * s3 + s_lut[ 1] * w3b;
        const float u1 = s_lut[ 2] * s3 + s_lut[ 3] * w3b;
        const float u2 = s_lut[ 4] * s3 + s_lut[ 5] * w3b;
        const float u3 = s_lut[ 6] * s3 + s_lut[ 7] * w3b;
        const float u4 = s_lut[ 8] * s3 + s_lut[ 9] * w3b;
        const float u5 = s_lut[10] * s3 + s_lut[11] * w3b;
        const float u6 = s_lut[12] * s3 + s_lut[13] * w3b;
        const float u7 = s_lut[14] * s3 + s_lut[15] * w3b;

        const float w2b = 1.0f - s2;
        const float v0 = u0 * s2 + u1 * w2b;
        const float v1 = u2 * s2 + u3 * w2b;
        const float v2 = u4 * s2 + u5 * w2b;
        const float v3 = u6 * s2 + u7 * w2b;

        const float w1b = 1.0f - s1;
        const float r0 = v0 * s1 + v1 * w1b;
        const float r1 = v2 * s1 + v3 * w1b;

        const float lut_out = r0 * s0 + r1 * (1.0f - s0);

        out[tile * TILE_ROWS + tid] = s_mix[0] * lut_out + s_mix[1] * ao1 + s_mix[2] * ao2;

        __syncthreads();   // all reads of buf done before it's refilled next iter
        buf ^= 1;
    }
}

extern "C" void kernel_launch(void* const* d_in, const int* in_sizes, int n_in,
                              void* d_out, int out_size)
{
    const float* x   = (const float*)d_in[0];   // [B, 64]
    const float* cp  = (const float*)d_in[1];   // [64, 4]
    const float* lut = (const float*)d_in[2];   // 16
    const float* mix = (const float*)d_in[3];   // 3
    float* out = (float*)d_out;

    const int B      = in_sizes[0] / 64;
    const int ntiles = B / TILE_ROWS;           // 8192

    const int smem_bytes = (2 * STAGE_F4 + 64) * sizeof(float4) + 24 * sizeof(float);

    static bool attr_set = false;               // idempotent, host-side only
    if (!attr_set) {
        cudaFuncSetAttribute(lab_fused_kernel,
                             cudaFuncAttributeMaxDynamicSharedMemorySize, smem_bytes);
        attr_set = true;
    }

    int grid = 444;                             // 3 CTAs/SM x 148 SMs, one wave
    if (grid > ntiles) grid = ntiles;

    lab_fused_kernel<<<grid, NTHREADS, smem_bytes>>>(x, cp, lut, mix, out, ntiles);
}

// round 6
// speedup vs baseline: 4.3555x; 1.0968x over previous
#include <cuda_runtime.h>
#include <cuda_bf16.h>
#include <cstdint>

// B = 1048576 rows, C = 64, K = 4.
// out[b] = mix0*lut(s) + mix1*clip(s0+s1+s2-2,0,1) + mix2*(s0+s1+s2>=2)
// with s = x[b,:] @ softmax(cp, axis=0).
//
// Round-6: bulk-copy (TMA) double-buffered pipeline, CORRECT pairing.
// Linear smem tiles + rotated per-lane reads xr[(f+tid)&15] (conflict-free);
// probs stored TRANSPOSED (probsT[k][c], 4x64) so the matching probs group
// probsT_k[(f+tid)&15] is also a conflict-free LDS.128 per k.

#define NTHREADS    128
#define TILE_ROWS   128
#define STAGE_F4    (TILE_ROWS * 16)          // 2048 float4 = 32 KB
#define STAGE_BYTES (STAGE_F4 * 16)

__device__ __forceinline__ void mbar_init(void* bar, unsigned count) {
    unsigned b = (unsigned)__cvta_generic_to_shared(bar);
    asm volatile("mbarrier.init.shared.b64 [%0], %1;" :: "r"(b), "r"(count) : "memory");
}
__device__ __forceinline__ void mbar_expect_tx(void* bar, unsigned bytes) {
    unsigned b = (unsigned)__cvta_generic_to_shared(bar);
    asm volatile("mbarrier.arrive.expect_tx.shared.b64 _, [%0], %1;"
                 :: "r"(b), "r"(bytes) : "memory");
}
__device__ __forceinline__ void mbar_wait_acq(void* bar, unsigned parity) {
    unsigned b = (unsigned)__cvta_generic_to_shared(bar);
    asm volatile(
        "{\n\t"
        ".reg .pred P;\n\t"
        "WAIT_%=:\n\t"
        "mbarrier.try_wait.parity.acquire.cta.shared::cta.b64 P, [%0], %1;\n\t"
        "@!P bra WAIT_%=;\n\t"
        "}"
        :: "r"(b), "r"(parity) : "memory");
}
__device__ __forceinline__ void fence_proxy_async_cta() {
    asm volatile("fence.proxy.async.shared::cta;" ::: "memory");
}
__device__ __forceinline__ void cp_bulk(void* smem_dst, const void* gsrc,
                                        unsigned bytes, void* bar) {
    unsigned s = (unsigned)__cvta_generic_to_shared(smem_dst);
    unsigned b = (unsigned)__cvta_generic_to_shared(bar);
    asm volatile(
        "cp.async.bulk.shared::cta.global.mbarrier::complete_tx::bytes "
        "[%0], [%1], %2, [%3];"
        :: "r"(s), "l"(gsrc), "r"(bytes), "r"(b) : "memory");
}

extern __shared__ float4 g_smem[];
// layout: [2*STAGE_F4] x tiles | [64] probsT (4 rows x 16 float4) |
//         [64] exp scratch      | tail floats (lut 16, mix 3, inv 4)

__global__ void __launch_bounds__(NTHREADS)
lab_fused_kernel(const float* __restrict__ x,
                 const float* __restrict__ cp,    // [64,4]
                 const float* __restrict__ lut,   // 16
                 const float* __restrict__ mix,   // 3
                 float* __restrict__ out,
                 int ntiles)
{
    float4* s_x      = g_smem;
    float4* s_probsT = g_smem + 2 * STAGE_F4;            // probsT[k*16 + g]
    float*  s_probsT_f = reinterpret_cast<float*>(s_probsT);
    float*  s_exp    = reinterpret_cast<float*>(s_probsT + 64);   // 256 floats
    float*  s_tail   = s_exp + 256;
    float*  s_lut    = s_tail;        // 16
    float*  s_mix    = s_tail + 16;   // 3
    float*  s_inv    = s_tail + 20;   // 4

    __shared__ __align__(8) uint64_t s_bar[2];

    const int tid = threadIdx.x;

    // ---- per-block parameter prep (once) ----
    s_exp[tid]       = __expf(cp[tid]);
    s_exp[tid + 128] = __expf(cp[tid + 128]);
    if (tid < 16) s_lut[tid] = 1.0f / (1.0f + __expf(-lut[tid]));
    if (tid == 32) {
        float m0 = __expf(mix[0]), m1 = __expf(mix[1]), m2 = __expf(mix[2]);
        float inv = 1.0f / (m0 + m1 + m2);
        s_mix[0] = m0 * inv; s_mix[1] = m1 * inv; s_mix[2] = m2 * inv;
    }
    if (tid == 0) {
        mbar_init(&s_bar[0], 1);
        mbar_init(&s_bar[1], 1);
    }
    __syncthreads();
    if (tid == 0) fence_proxy_async_cta();       // order mbar init before TMA use
    __syncthreads();

    if (tid < 32) {                              // column sums: lane t sums k = t%4
        float acc = 0.0f;
        #pragma unroll
        for (int i = 0; i < 8; ++i) acc += s_exp[tid + 32 * i];
        #pragma unroll
        for (int off = 16; off >= 4; off >>= 1)
            acc += __shfl_down_sync(0xffffffffu, acc, off);
        if (tid < 4) s_inv[tid] = 1.0f / acc;
    }
    __syncthreads();

    // transpose-normalize: element (c,k) -> probsT[k*64 + c]
    {
        int c0 = tid >> 2, k0 = tid & 3;
        s_probsT_f[k0 * 64 + c0] = s_exp[tid] * s_inv[k0];
        int t1 = tid + 128, c1 = t1 >> 2, k1 = t1 & 3;
        s_probsT_f[k1 * 64 + c1] = s_exp[t1] * s_inv[k1];
    }
    __syncthreads();

    const char* __restrict__ xb = reinterpret_cast<const char*>(x);
    const int stride = gridDim.x;

    // ---- software pipeline: one 32KB bulk copy per tile, double-buffered ----
    int tile = blockIdx.x;
    if (tid == 0 && tile < ntiles) {
        mbar_expect_tx(&s_bar[0], STAGE_BYTES);
        cp_bulk(s_x, xb + (size_t)tile * STAGE_BYTES, STAGE_BYTES, &s_bar[0]);
    }

    const float4* __restrict__ q0 = s_probsT;         // k = 0
    const float4* __restrict__ q1 = s_probsT + 16;    // k = 1
    const float4* __restrict__ q2 = s_probsT + 32;    // k = 2
    const float4* __restrict__ q3 = s_probsT + 48;    // k = 3

    int buf = 0;
    unsigned ph0 = 0, ph1 = 0;                   // per-stage phase parity
    for (; tile < ntiles; tile += stride) {
        const int nxt = tile + stride;
        if (tid == 0 && nxt < ntiles) {          // prefetch into other buffer
            fence_proxy_async_cta();             // prior LDS reads -> next TMA write
            mbar_expect_tx(&s_bar[buf ^ 1], STAGE_BYTES);
            cp_bulk(s_x + (buf ^ 1) * STAGE_F4,
                    xb + (size_t)nxt * STAGE_BYTES, STAGE_BYTES, &s_bar[buf ^ 1]);
        }

        // wait (acquire) for current buffer: TMA writes visible to LDS
        if (buf == 0) { mbar_wait_acq(&s_bar[0], ph0); ph0 ^= 1; }
        else          { mbar_wait_acq(&s_bar[1], ph1); ph1 ^= 1; }

        const float4* __restrict__ xr = s_x + buf * STAGE_F4 + tid * 16;
        float a0 = 0.0f, a1 = 0.0f, a2 = 0.0f, a3 = 0.0f;
        #pragma unroll
        for (int f = 0; f < 16; ++f) {
            const int g = (f + tid) & 15;        // rotated: conflict-free phases
            const float4 xv = xr[g];             // x columns 4g..4g+3
            const float4 b0 = q0[g];             // probsT matches the SAME g
            const float4 b1 = q1[g];
            const float4 b2 = q2[g];
            const float4 b3 = q3[g];
            a0 = fmaf(xv.x, b0.x, a0); a0 = fmaf(xv.y, b0.y, a0);
            a0 = fmaf(xv.z, b0.z, a0); a0 = fmaf(xv.w, b0.w, a0);
            a1 = fmaf(xv.x, b1.x, a1); a1 = fmaf(xv.y, b1.y, a1);
            a1 = fmaf(xv.z, b1.z, a1); a1 = fmaf(xv.w, b1.w, a1);
            a2 = fmaf(xv.x, b2.x, a2); a2 = fmaf(xv.y, b2.y, a2);
            a2 = fmaf(xv.z, b2.z, a2); a2 = fmaf(xv.w, b2.w, a2);
            a3 = fmaf(xv.x, b3.x, a3); a3 = fmaf(xv.y, b3.y, a3);
            a3 = fmaf(xv.z, b3.z, a3); a3 = fmaf(xv.w, b3.w, a3);
        }

        const float s0 = a0, s1 = a1, s2 = a2, s3 = a3;

        // addition path
        const float add = s0 + s1 + s2;
        const float ao1 = fminf(fmaxf(add - 2.0f, 0.0f), 1.0f);
        const float ao2 = (add >= 2.0f) ? 1.0f : 0.0f;

        // multilinear contraction over sigmoid(lut)[2,2,2,2]; bit0 -> s, bit1 -> 1-s
        const float w3b = 1.0f - s3;
        const float u0 = s_lut[ 0] * s3 + s_lut[ 1] * w3b;
        const float u1 = s_lut[ 2] * s3 + s_lut[ 3] * w3b;
        const float u2 = s_lut[ 4] * s3 + s_lut[ 5] * w3b;
        const float u3 = s_lut[ 6] * s3 + s_lut[ 7] * w3b;
        const float u4 = s_lut[ 8] * s3 + s_lut[ 9] * w3b;
        const float u5 = s_lut[10] * s3 + s_lut[11] * w3b;
        const float u6 = s_lut[12] * s3 + s_lut[13] * w3b;
        const float u7 = s_lut[14] * s3 + s_lut[15] * w3b;

        const float w2b = 1.0f - s2;
        const float v0 = u0 * s2 + u1 * w2b;
        const float v1 = u2 * s2 + u3 * w2b;
        const float v2 = u4 * s2 + u5 * w2b;
        const float v3 = u6 * s2 + u7 * w2b;

        const float w1b = 1.0f - s1;
        const float r0 = v0 * s1 + v1 * w1b;
        const float r1 = v2 * s1 + v3 * w1b;

        const float lut_out = r0 * s0 + r1 * (1.0f - s0);

        out[tile * TILE_ROWS + tid] = s_mix[0] * lut_out + s_mix[1] * ao1 + s_mix[2] * ao2;

        __syncthreads();   // all reads of buf done before it is refilled
        buf ^= 1;
    }
}

extern "C" void kernel_launch(void* const* d_in, const int* in_sizes, int n_in,
                              void* d_out, int out_size)
{
    const float* x   = (const float*)d_in[0];   // [B, 64]
    const float* cp  = (const float*)d_in[1];   // [64, 4]
    const float* lut = (const float*)d_in[2];   // 16
    const float* mix = (const float*)d_in[3];   // 3
    float* out = (float*)d_out;

    const int B      = in_sizes[0] / 64;
    const int ntiles = B / TILE_ROWS;           // 8192

    const int smem_bytes = (2 * STAGE_F4 + 64) * sizeof(float4)
                         + (256 + 24) * sizeof(float);

    static bool attr_set = false;               // idempotent, host-side only
    if (!attr_set) {
        cudaFuncSetAttribute(lab_fused_kernel,
                             cudaFuncAttributeMaxDynamicSharedMemorySize, smem_bytes);
        attr_set = true;
    }

    int grid = 444;                             // 3 CTAs/SM x 148 SMs, one wave
    if (grid > ntiles) grid = ntiles;

    lab_fused_kernel<<<grid, NTHREADS, smem_bytes>>>(x, cp, lut, mix, out, ntiles);
}